// round 15
// baseline (speedup 1.0000x reference)
#include <cuda_runtime.h>
#include <cuda_bf16.h>
#include <math.h>
#include <stdint.h>

#define B_  2
#define T_  1024
#define BT  2048
#define D_  768
#define H_  12
#define DH_ 64
#define FF_ 3072
#define L_  12
#define S_  8
#define V_  1024
#define E3  2304   // 3*D

typedef __nv_bfloat16 bf16;

// ---------------- scratch -------------------------------------------------
__device__ __align__(16) float g_x   [BT * D_];

__device__ __align__(16) bf16 g_h_hi [BT * D_];
__device__ __align__(16) bf16 g_h_lo [BT * D_];
__device__ __align__(16) bf16 g_at_hi[BT * D_];
__device__ __align__(16) bf16 g_at_lo[BT * D_];
__device__ __align__(16) bf16 g_ff_hi[BT * FF_];
__device__ __align__(16) bf16 g_ff_lo[BT * FF_];
__device__ __align__(16) bf16 g_qkv_hi[BT * E3];
__device__ __align__(16) bf16 g_qkv_lo[BT * E3];

// weight splits
__device__ __align__(16) bf16 g_qkvw_hi [L_ * E3 * D_];
__device__ __align__(16) bf16 g_qkvw_lo [L_ * E3 * D_];
__device__ __align__(16) bf16 g_projw_hi[L_ * D_ * D_];
__device__ __align__(16) bf16 g_projw_lo[L_ * D_ * D_];
__device__ __align__(16) bf16 g_gatew_hi[L_ * FF_ * D_];
__device__ __align__(16) bf16 g_gatew_lo[L_ * FF_ * D_];
__device__ __align__(16) bf16 g_upw_hi  [L_ * FF_ * D_];
__device__ __align__(16) bf16 g_upw_lo  [L_ * FF_ * D_];
__device__ __align__(16) bf16 g_downw_hi[L_ * D_ * FF_];
__device__ __align__(16) bf16 g_downw_lo[L_ * D_ * FF_];

// ---------------- helpers --------------------------------------------------
__device__ __forceinline__ uint32_t smem_u32(const void* p) {
    uint32_t a;
    asm("{ .reg .u64 t; cvta.to.shared.u64 t, %1; cvt.u32.u64 %0, t; }" : "=r"(a) : "l"(p));
    return a;
}
__device__ __forceinline__ void cp16(uint32_t dst, const void* src) {
    asm volatile("cp.async.cg.shared.global [%0], [%1], 16;" :: "r"(dst), "l"(src));
}
__device__ __forceinline__ void cp_commit() {
    asm volatile("cp.async.commit_group;" ::: "memory");
}
template<int N>
__device__ __forceinline__ void cp_wait() {
    asm volatile("cp.async.wait_group %0;" :: "n"(N) : "memory");
}
__device__ __forceinline__ void ldsm4(uint32_t& r0, uint32_t& r1, uint32_t& r2, uint32_t& r3,
                                      uint32_t addr) {
    asm volatile("ldmatrix.sync.aligned.m8n8.x4.shared.b16 {%0,%1,%2,%3}, [%4];"
                 : "=r"(r0), "=r"(r1), "=r"(r2), "=r"(r3) : "r"(addr));
}
__device__ __forceinline__ void ldsm4t(uint32_t& r0, uint32_t& r1, uint32_t& r2, uint32_t& r3,
                                       uint32_t addr) {
    asm volatile("ldmatrix.sync.aligned.m8n8.x4.trans.shared.b16 {%0,%1,%2,%3}, [%4];"
                 : "=r"(r0), "=r"(r1), "=r"(r2), "=r"(r3) : "r"(addr));
}
__device__ __forceinline__ void mma_bf16(float* c, const uint32_t* a, const uint32_t* b) {
    asm volatile(
        "mma.sync.aligned.m16n8k16.row.col.f32.bf16.bf16.f32 "
        "{%0,%1,%2,%3}, {%4,%5,%6,%7}, {%8,%9}, {%0,%1,%2,%3};"
        : "+f"(c[0]), "+f"(c[1]), "+f"(c[2]), "+f"(c[3])
        : "r"(a[0]), "r"(a[1]), "r"(a[2]), "r"(a[3]), "r"(b[0]), "r"(b[1]));
}
#define SWZ(x) ((x) ^ (((x) >> 3) & 0x70))

// fast exp on FMA pipe
__device__ __forceinline__ float fexp(float x) {
    x = fmaxf(fminf(x, 80.f), -80.f);
    float t = x * 1.4426950408889634f;
    float fl = floorf(t);
    float f = t - fl;
    float p = 1.3333558e-3f;
    p = fmaf(p, f, 9.6181291e-3f);
    p = fmaf(p, f, 5.5504109e-2f);
    p = fmaf(p, f, 2.4022651e-1f);
    p = fmaf(p, f, 6.9314718e-1f);
    p = fmaf(p, f, 1.0f);
    int e = (int)fl;
    return __int_as_float(__float_as_int(p) + (e << 23));
}
__device__ __forceinline__ float fexp2(float t) {
    t = fmaxf(fminf(t, 80.f), -80.f);
    float fl = floorf(t);
    float f = t - fl;
    float p = 1.3333558e-3f;
    p = fmaf(p, f, 9.6181291e-3f);
    p = fmaf(p, f, 5.5504109e-2f);
    p = fmaf(p, f, 2.4022651e-1f);
    p = fmaf(p, f, 6.9314718e-1f);
    p = fmaf(p, f, 1.0f);
    int e = (int)fl;
    return __int_as_float(__float_as_int(p) + (e << 23));
}
__device__ __forceinline__ void split2(float x, bf16& h, bf16& l) {
    h = __float2bfloat16_rn(x);
    l = __float2bfloat16_rn(x - __bfloat162float(h));
}
__device__ __forceinline__ float silu(float g) {
    return g / (1.f + fexp(-g));
}
__device__ __forceinline__ uint32_t pack_bf2(bf16 a, bf16 b) {
    __nv_bfloat162 t = {a, b};
    return *(uint32_t*)&t;
}

// ---------------- fused weight split ----------------------------------------
#define N8_QKV  (L_ * E3 * D_ / 8)
#define N8_PROJ (L_ * D_ * D_ / 8)
#define N8_FF   (L_ * FF_ * D_ / 8)
#define N8_TOT  (N8_QKV + N8_PROJ + 3 * N8_FF)
__global__ void split_all_kernel(
    const float* __restrict__ q, const float* __restrict__ p,
    const float* __restrict__ gt, const float* __restrict__ u,
    const float* __restrict__ dn,
    bf16* __restrict__ qh, bf16* __restrict__ ql,
    bf16* __restrict__ ph, bf16* __restrict__ pl,
    bf16* __restrict__ gh, bf16* __restrict__ gl,
    bf16* __restrict__ uh, bf16* __restrict__ ul,
    bf16* __restrict__ dh, bf16* __restrict__ dl) {
    int i = blockIdx.x * blockDim.x + threadIdx.x;
    if (i >= N8_TOT) return;
    const float* src; bf16 *hi, *lo; int j;
    if (i < N8_QKV)                      { src = q;  hi = qh; lo = ql; j = i; }
    else if (i < N8_QKV + N8_PROJ)       { src = p;  hi = ph; lo = pl; j = i - N8_QKV; }
    else if (i < N8_QKV + N8_PROJ + N8_FF)       { src = gt; hi = gh; lo = gl; j = i - N8_QKV - N8_PROJ; }
    else if (i < N8_QKV + N8_PROJ + 2 * N8_FF)   { src = u;  hi = uh; lo = ul; j = i - N8_QKV - N8_PROJ - N8_FF; }
    else                                 { src = dn; hi = dh; lo = dl; j = i - N8_QKV - N8_PROJ - 2 * N8_FF; }
    float4 v0 = __ldcs((const float4*)src + 2 * (size_t)j);
    float4 v1 = __ldcs((const float4*)src + 2 * (size_t)j + 1);
    bf16 h[8], l[8];
    split2(v0.x, h[0], l[0]); split2(v0.y, h[1], l[1]);
    split2(v0.z, h[2], l[2]); split2(v0.w, h[3], l[3]);
    split2(v1.x, h[4], l[4]); split2(v1.y, h[5], l[5]);
    split2(v1.z, h[6], l[6]); split2(v1.w, h[7], l[7]);
    uint4 hv = make_uint4(pack_bf2(h[0], h[1]), pack_bf2(h[2], h[3]),
                          pack_bf2(h[4], h[5]), pack_bf2(h[6], h[7]));
    uint4 lv = make_uint4(pack_bf2(l[0], l[1]), pack_bf2(l[2], l[3]),
                          pack_bf2(l[4], l[5]), pack_bf2(l[6], l[7]));
    __stcs((uint4*)hi + j, hv);
    __stcs((uint4*)lo + j, lv);
}

// ---------------- embedding ------------------------------------------------
__global__ void embed_kernel(const int* __restrict__ tok,
                             const int* __restrict__ pos,
                             const float* __restrict__ intent,
                             const float* __restrict__ rvq,
                             const float* __restrict__ pe) {
    int i4 = blockIdx.x * blockDim.x + threadIdx.x;
    if (i4 >= BT * D_ / 4) return;
    int row = i4 / (D_ / 4), d4 = i4 % (D_ / 4);
    int b = row / T_;
    float4 acc = ((const float4*)(pe + (size_t)pos[row] * D_))[d4];
    float4 it = ((const float4*)(intent + (size_t)b * D_))[d4];
    acc.x += it.x; acc.y += it.y; acc.z += it.z; acc.w += it.w;
    const int* tk = tok + (size_t)row * S_;
#pragma unroll
    for (int s = 0; s < S_; s++) {
        float4 rv = ((const float4*)(rvq + ((size_t)s * V_ + tk[s]) * D_))[d4];
        acc.x += rv.x; acc.y += rv.y; acc.z += rv.z; acc.w += rv.w;
    }
    ((float4*)g_x)[i4] = acc;
}

// ---------------- rmsnorm -> hi/lo bf16 (warp per row) ----------------------
__global__ void rmsnorm_split_kernel(const float* __restrict__ src,
                                     const float* __restrict__ w,
                                     bf16* __restrict__ hi, bf16* __restrict__ lo) {
    int gw = (blockIdx.x * blockDim.x + threadIdx.x) >> 5;
    int lane = threadIdx.x & 31;
    const float4* x4 = (const float4*)(src + (size_t)gw * D_);
    const float4* w4 = (const float4*)w;
    float4 v[6];
    float ss = 0.f;
#pragma unroll
    for (int j = 0; j < 6; j++) {
        v[j] = x4[lane + 32 * j];
        ss += v[j].x * v[j].x + v[j].y * v[j].y + v[j].z * v[j].z + v[j].w * v[j].w;
    }
#pragma unroll
    for (int o = 16; o; o >>= 1) ss += __shfl_xor_sync(0xffffffffu, ss, o);
    float inv = rsqrtf(ss * (1.0f / D_) + 1e-6f);
    uint2* hp = (uint2*)(hi + (size_t)gw * D_);
    uint2* lp = (uint2*)(lo + (size_t)gw * D_);
#pragma unroll
    for (int j = 0; j < 6; j++) {
        float4 wv = w4[lane + 32 * j];
        float y0 = v[j].x * inv * wv.x, y1 = v[j].y * inv * wv.y;
        float y2 = v[j].z * inv * wv.z, y3 = v[j].w * inv * wv.w;
        bf16 h0, l0, h1, l1, h2, l2, h3, l3;
        split2(y0, h0, l0); split2(y1, h1, l1);
        split2(y2, h2, l2); split2(y3, h3, l3);
        hp[lane + 32 * j] = make_uint2(pack_bf2(h0, h1), pack_bf2(h2, h3));
        lp[lane + 32 * j] = make_uint2(pack_bf2(l0, l1), pack_bf2(l2, l3));
    }
}

// ---------------- HMMA bf16x3 GEMM (single-sync pipeline) -------------------
// MODE 1: C = res + A*W^T fp32; MODE 3: A*W^T -> split bf16 out
template<int BM, int BN, int WM, int WN, int MODE, int NS>
__global__ __launch_bounds__(WM * WN * 32)
void gemm_mma(const bf16* __restrict__ Ah, const bf16* __restrict__ Al,
              const bf16* __restrict__ Wh, const bf16* __restrict__ Wl,
              float* __restrict__ C, const float* __restrict__ res,
              bf16* __restrict__ out_hi, bf16* __restrict__ out_lo,
              int N, int K) {
    constexpr int NT   = WM * WN * 32;
    constexpr int WTM  = BM / WM;
    constexpr int WTN  = BN / WN;
    constexpr int MT   = WTM / 16;
    constexpr int NTt  = WTN / 8;
    constexpr int ASZ  = BM * 128;
    constexpr int WSZ  = BN * 128;
    constexpr int STAGE = 2 * ASZ + 2 * WSZ;

    extern __shared__ char smem[];
    uint32_t sb = smem_u32(smem);
    int tid = threadIdx.x, lane = tid & 31, w = tid >> 5;
    int mw = w / WN, nw = w % WN;
    int m0 = blockIdx.y * BM, n0 = blockIdx.x * BN;

    float c[MT][NTt][4];
#pragma unroll
    for (int i = 0; i < MT; i++)
#pragma unroll
        for (int j = 0; j < NTt; j++)
#pragma unroll
            for (int q = 0; q < 4; q++) c[i][j][q] = 0.f;

    int nst = K >> 6;
    int a_row = (lane & 15);
    int a_kof = (lane >> 4) * 16;
    int b_row = (lane & 7) + ((lane >> 4) << 3);
    int b_kof = ((lane >> 3) & 1) * 16;

    auto load_stage = [&](int stage_idx, int k0) {
        uint32_t buf = sb + (stage_idx % NS) * STAGE;
#pragma unroll
        for (int j = 0; j < BM * 8 / NT; j++) {
            int idx = tid + j * NT;
            int row = idx >> 3, q = idx & 7;
            uint32_t so = SWZ(row * 128 + q * 16);
            size_t ga = (size_t)(m0 + row) * K + k0 + q * 8;
            cp16(buf + so, Ah + ga);
            cp16(buf + ASZ + so, Al + ga);
        }
#pragma unroll
        for (int j = 0; j < BN * 8 / NT; j++) {
            int idx = tid + j * NT;
            int row = idx >> 3, q = idx & 7;
            uint32_t so = SWZ(row * 128 + q * 16);
            size_t gw = (size_t)(n0 + row) * K + k0 + q * 8;
            cp16(buf + 2 * ASZ + so, Wh + gw);
            cp16(buf + 2 * ASZ + WSZ + so, Wl + gw);
        }
        cp_commit();
    };

    load_stage(0, 0);

    for (int i = 0; i < nst; i++) {
        cp_wait<0>();            // stage i complete (all issued groups)
        __syncthreads();         // publish + all warps past compute of i-1
        if (i + 1 < nst) load_stage(i + 1, (i + 1) << 6);   // overlaps compute(i)

        uint32_t buf = sb + (i % NS) * STAGE;
        uint32_t sAh = buf, sAl = buf + ASZ, sWh = buf + 2 * ASZ, sWl = buf + 2 * ASZ + WSZ;

#pragma unroll
        for (int ks = 0; ks < 4; ks++) {
            uint32_t ah[MT][4], al[MT][4], bh[NTt][2], bl[NTt][2];
#pragma unroll
            for (int mt = 0; mt < MT; mt++) {
                uint32_t off = SWZ((mw * WTM + mt * 16 + a_row) * 128 + ks * 32 + a_kof);
                ldsm4(ah[mt][0], ah[mt][1], ah[mt][2], ah[mt][3], sAh + off);
                ldsm4(al[mt][0], al[mt][1], al[mt][2], al[mt][3], sAl + off);
            }
#pragma unroll
            for (int p = 0; p < NTt / 2; p++) {
                uint32_t off = SWZ((nw * WTN + p * 16 + b_row) * 128 + ks * 32 + b_kof);
                ldsm4(bh[2*p][0], bh[2*p][1], bh[2*p+1][0], bh[2*p+1][1], sWh + off);
                ldsm4(bl[2*p][0], bl[2*p][1], bl[2*p+1][0], bl[2*p+1][1], sWl + off);
            }
#pragma unroll
            for (int mt = 0; mt < MT; mt++)
#pragma unroll
                for (int nt = 0; nt < NTt; nt++) {
                    mma_bf16(c[mt][nt], ah[mt], bh[nt]);
                    mma_bf16(c[mt][nt], ah[mt], bl[nt]);
                    mma_bf16(c[mt][nt], al[mt], bh[nt]);
                }
        }
    }

    int g = lane >> 2, tig = lane & 3;
#pragma unroll
    for (int mt = 0; mt < MT; mt++) {
        int row = m0 + mw * WTM + mt * 16 + g;
#pragma unroll
        for (int nt = 0; nt < NTt; nt++) {
            int col = n0 + nw * WTN + nt * 8 + tig * 2;
            size_t o0 = (size_t)row * N + col;
            size_t o1 = o0 + (size_t)8 * N;
            float2 v0 = make_float2(c[mt][nt][0], c[mt][nt][1]);
            float2 v1 = make_float2(c[mt][nt][2], c[mt][nt][3]);
            if (MODE == 1) {
                float2 r0 = *(const float2*)&res[o0];
                float2 r1 = *(const float2*)&res[o1];
                v0.x += r0.x; v0.y += r0.y; v1.x += r1.x; v1.y += r1.y;
                *(float2*)&C[o0] = v0;
                *(float2*)&C[o1] = v1;
            } else {
                bf16 h00, l00, h01, l01, h10, l10, h11, l11;
                split2(v0.x, h00, l00); split2(v0.y, h01, l01);
                split2(v1.x, h10, l10); split2(v1.y, h11, l11);
                *(__nv_bfloat162*)&out_hi[o0] = {h00, h01};
                *(__nv_bfloat162*)&out_hi[o1] = {h10, h11};
                *(__nv_bfloat162*)&out_lo[o0] = {l00, l01};
                *(__nv_bfloat162*)&out_lo[o1] = {l10, l11};
            }
        }
    }
}

// 128-thread shapes for 2 CTAs/SM
#define GEMM_Q   gemm_mma<128, 64, 2, 2, 3, 2>
#define GEMM_P   gemm_mma<128, 64, 2, 2, 1, 2>
#define SMEM_QP  (2 * (2 * 128 * 128 + 2 * 64 * 128))   // 98304

// ---------------- fused gate+up GEMM (single-sync pipeline) -----------------
#define GU_ASZ  8192
#define GU_STAGE (6 * GU_ASZ)
#define SMEM_GU (2 * GU_STAGE)            // 98304
__global__ __launch_bounds__(128)
void gemm_gu(const bf16* __restrict__ Ah, const bf16* __restrict__ Al,
             const bf16* __restrict__ Gh, const bf16* __restrict__ Gl,
             const bf16* __restrict__ Uh, const bf16* __restrict__ Ul,
             bf16* __restrict__ out_hi, bf16* __restrict__ out_lo,
             int N, int K) {
    extern __shared__ char smem[];
    uint32_t sb = smem_u32(smem);
    int tid = threadIdx.x, lane = tid & 31, w = tid >> 5;
    int mw = w >> 1, nw = w & 1;
    int m0 = blockIdx.y * 64, n0 = blockIdx.x * 64;

    float cg[2][4][4], cu[2][4][4];
#pragma unroll
    for (int i = 0; i < 2; i++)
#pragma unroll
        for (int j = 0; j < 4; j++)
#pragma unroll
            for (int q = 0; q < 4; q++) { cg[i][j][q] = 0.f; cu[i][j][q] = 0.f; }

    int nst = K >> 6;
    int a_row = lane & 15, a_kof = (lane >> 4) * 16;
    int b_row = (lane & 7) + ((lane >> 4) << 3), b_kof = ((lane >> 3) & 1) * 16;

    auto load_stage = [&](int si, int k0) {
        uint32_t buf = sb + (si & 1) * GU_STAGE;
#pragma unroll
        for (int j = 0; j < 4; j++) {
            int idx = tid + j * 128;
            int row = idx >> 3, q = idx & 7;
            uint32_t so = SWZ(row * 128 + q * 16);
            size_t ga = (size_t)(m0 + row) * K + k0 + q * 8;
            size_t gw = (size_t)(n0 + row) * K + k0 + q * 8;
            cp16(buf + so, Ah + ga);
            cp16(buf + GU_ASZ + so, Al + ga);
            cp16(buf + 2 * GU_ASZ + so, Gh + gw);
            cp16(buf + 3 * GU_ASZ + so, Gl + gw);
            cp16(buf + 4 * GU_ASZ + so, Uh + gw);
            cp16(buf + 5 * GU_ASZ + so, Ul + gw);
        }
        cp_commit();
    };

    load_stage(0, 0);

    for (int i = 0; i < nst; i++) {
        cp_wait<0>();
        __syncthreads();
        if (i + 1 < nst) load_stage(i + 1, (i + 1) << 6);

        uint32_t buf = sb + (i & 1) * GU_STAGE;

#pragma unroll
        for (int ks = 0; ks < 4; ks++) {
            uint32_t ah[2][4], al[2][4], bh[4][2], bl[4][2];
#pragma unroll
            for (int mt = 0; mt < 2; mt++) {
                uint32_t off = SWZ((mw * 32 + mt * 16 + a_row) * 128 + ks * 32 + a_kof);
                ldsm4(ah[mt][0], ah[mt][1], ah[mt][2], ah[mt][3], buf + off);
                ldsm4(al[mt][0], al[mt][1], al[mt][2], al[mt][3], buf + GU_ASZ + off);
            }
#pragma unroll
            for (int p = 0; p < 2; p++) {
                uint32_t off = SWZ((nw * 32 + p * 16 + b_row) * 128 + ks * 32 + b_kof);
                ldsm4(bh[2*p][0], bh[2*p][1], bh[2*p+1][0], bh[2*p+1][1], buf + 2 * GU_ASZ + off);
                ldsm4(bl[2*p][0], bl[2*p][1], bl[2*p+1][0], bl[2*p+1][1], buf + 3 * GU_ASZ + off);
            }
#pragma unroll
            for (int mt = 0; mt < 2; mt++)
#pragma unroll
                for (int nt = 0; nt < 4; nt++) {
                    mma_bf16(cg[mt][nt], ah[mt], bh[nt]);
                    mma_bf16(cg[mt][nt], ah[mt], bl[nt]);
                    mma_bf16(cg[mt][nt], al[mt], bh[nt]);
                }
#pragma unroll
            for (int p = 0; p < 2; p++) {
                uint32_t off = SWZ((nw * 32 + p * 16 + b_row) * 128 + ks * 32 + b_kof);
                ldsm4(bh[2*p][0], bh[2*p][1], bh[2*p+1][0], bh[2*p+1][1], buf + 4 * GU_ASZ + off);
                ldsm4(bl[2*p][0], bl[2*p][1], bl[2*p+1][0], bl[2*p+1][1], buf + 5 * GU_ASZ + off);
            }
#pragma unroll
            for (int mt = 0; mt < 2; mt++)
#pragma unroll
                for (int nt = 0; nt < 4; nt++) {
                    mma_bf16(cu[mt][nt], ah[mt], bh[nt]);
                    mma_bf16(cu[mt][nt], ah[mt], bl[nt]);
                    mma_bf16(cu[mt][nt], al[mt], bh[nt]);
                }
        }
    }

    int g = lane >> 2, tig = lane & 3;
#pragma unroll
    for (int mt = 0; mt < 2; mt++) {
        int row = m0 + mw * 32 + mt * 16 + g;
#pragma unroll
        for (int nt = 0; nt < 4; nt++) {
            int col = n0 + nw * 32 + nt * 8 + tig * 2;
            size_t o0 = (size_t)row * N + col;
            size_t o1 = o0 + (size_t)8 * N;
            float y00 = silu(cg[mt][nt][0]) * cu[mt][nt][0];
            float y01 = silu(cg[mt][nt][1]) * cu[mt][nt][1];
            float y10 = silu(cg[mt][nt][2]) * cu[mt][nt][2];
            float y11 = silu(cg[mt][nt][3]) * cu[mt][nt][3];
            bf16 h00, l00, h01, l01, h10, l10, h11, l11;
            split2(y00, h00, l00); split2(y01, h01, l01);
            split2(y10, h10, l10); split2(y11, h11, l11);
            *(__nv_bfloat162*)&out_hi[o0] = {h00, h01};
            *(__nv_bfloat162*)&out_hi[o1] = {h10, h11};
            *(__nv_bfloat162*)&out_lo[o0] = {l00, l01};
            *(__nv_bfloat162*)&out_lo[o1] = {l10, l11};
        }
    }
}

// ---------------- HMMA flash attention (AQ=64, 3-stage, single-sync) --------
#define AQ 64
#define AK 64
#define ATT_SMEM (16384 + 3 * 32768)    // 114688
#define SC2 0.18033688f    // 0.125 * log2(e)
__global__ __launch_bounds__(128)
void attn_mma() {
    extern __shared__ char smem[];
    uint32_t sb = smem_u32(smem);
    int tid = threadIdx.x, lane = tid & 31, w = tid >> 5;
    int bid = blockIdx.x;
    int bh = bid % (B_ * H_);
    int qt = (T_ / AQ - 1) - bid / (B_ * H_);
    int h = bh % H_, b = bh / H_;
    int q0 = qt * AQ;
    int wq = w * 16;
    int g = lane >> 2, tig = lane & 3;
    int a_row = lane & 15, a_kof = (lane >> 4) * 16;
    int b_row = (lane & 7) + ((lane >> 4) << 3), b_kof = ((lane >> 3) & 1) * 16;
    int vr_base = (lane & 7) + ((lane >> 3) & 1) * 8;
    int vc_base = ((lane >> 4) & 1) * 16;

    {
        size_t base = (size_t)(b * T_ + q0) * E3 + h * 64;
#pragma unroll
        for (int j = 0; j < 4; j++) {
            int idx = tid + j * 128;
            int row = idx >> 3, q = idx & 7;
            uint32_t so = SWZ(row * 128 + q * 16);
            cp16(sb + so,        g_qkv_hi + base + (size_t)row * E3 + q * 8);
            cp16(sb + 8192 + so, g_qkv_lo + base + (size_t)row * E3 + q * 8);
        }
        cp_commit();
    }

    auto load_kv = [&](int t) {
        uint32_t st = sb + 16384 + (t % 3) * 32768;
        int k0 = t * AK;
        size_t kb = (size_t)(b * T_ + k0) * E3 + D_ + h * 64;
#pragma unroll
        for (int j = 0; j < 4; j++) {
            int idx = tid + j * 128;
            int row = idx >> 3, q = idx & 7;
            uint32_t so = SWZ(row * 128 + q * 16);
            cp16(st + so,         g_qkv_hi + kb + (size_t)row * E3 + q * 8);
            cp16(st + 8192 + so,  g_qkv_lo + kb + (size_t)row * E3 + q * 8);
            cp16(st + 16384 + so, g_qkv_hi + kb + D_ + (size_t)row * E3 + q * 8);
            cp16(st + 24576 + so, g_qkv_lo + kb + D_ + (size_t)row * E3 + q * 8);
        }
        cp_commit();
    };

    int ntiles = qt + 1;
    load_kv(0);
    if (ntiles > 1) load_kv(1);

    float co[8][4];
#pragma unroll
    for (int nt = 0; nt < 8; nt++)
#pragma unroll
        for (int q = 0; q < 4; q++) co[nt][q] = 0.f;
    float m0v = -INFINITY, m1v = -INFINITY, l0 = 0.f, l1 = 0.f;

    for (int t = 0; t < ntiles; t++) {
        if (t + 1 < ntiles) { cp_wait<1>(); }   // stage t done, t+1 may be in flight
        else                { cp_wait<0>(); }
        __syncthreads();                        // publish + all warps past compute t-1
        if (t + 2 < ntiles) load_kv(t + 2);     // into buffer freed at t-1
        uint32_t st = sb + 16384 + (t % 3) * 32768;

        float cs[8][4];
#pragma unroll
        for (int nt = 0; nt < 8; nt++)
#pragma unroll
            for (int q = 0; q < 4; q++) cs[nt][q] = 0.f;
#pragma unroll
        for (int ks = 0; ks < 4; ks++) {
            uint32_t ah[4], al[4], kh[8][2], kl[8][2];
            uint32_t offA = SWZ((wq + a_row) * 128 + ks * 32 + a_kof);
            ldsm4(ah[0], ah[1], ah[2], ah[3], sb + offA);
            ldsm4(al[0], al[1], al[2], al[3], sb + 8192 + offA);
#pragma unroll
            for (int p = 0; p < 4; p++) {
                uint32_t offB = SWZ((p * 16 + b_row) * 128 + ks * 32 + b_kof);
                ldsm4(kh[2*p][0], kh[2*p][1], kh[2*p+1][0], kh[2*p+1][1], st + offB);
                ldsm4(kl[2*p][0], kl[2*p][1], kl[2*p+1][0], kl[2*p+1][1], st + 8192 + offB);
            }
#pragma unroll
            for (int nt = 0; nt < 8; nt++) {
                mma_bf16(cs[nt], ah, kh[nt]);
                mma_bf16(cs[nt], ah, kl[nt]);
                mma_bf16(cs[nt], al, kh[nt]);
            }
        }

        int k0 = t * AK;
        bool partial = (t == qt);
        int r0 = q0 + wq + g, r1 = r0 + 8;
#pragma unroll
        for (int nt = 0; nt < 8; nt++) {
#pragma unroll
            for (int q = 0; q < 4; q++) cs[nt][q] *= SC2;
            if (partial) {
                int c0 = k0 + nt * 8 + 2 * tig, c1 = c0 + 1;
                if (c0 > r0) cs[nt][0] = -INFINITY;
                if (c1 > r0) cs[nt][1] = -INFINITY;
                if (c0 > r1) cs[nt][2] = -INFINITY;
                if (c1 > r1) cs[nt][3] = -INFINITY;
            }
        }

        float mx0 = -INFINITY, mx1 = -INFINITY;
#pragma unroll
        for (int nt = 0; nt < 8; nt++) {
            mx0 = fmaxf(mx0, fmaxf(cs[nt][0], cs[nt][1]));
            mx1 = fmaxf(mx1, fmaxf(cs[nt][2], cs[nt][3]));
        }
        mx0 = fmaxf(mx0, __shfl_xor_sync(0xffffffffu, mx0, 1));
        mx0 = fmaxf(mx0, __shfl_xor_sync(0xffffffffu, mx0, 2));
        mx1 = fmaxf(mx1, __shfl_xor_sync(0xffffffffu, mx1, 1));
        mx1 = fmaxf(mx1, __shfl_xor_sync(0xffffffffu, mx1, 2));

        float nm0 = fmaxf(m0v, mx0), nm1 = fmaxf(m1v, mx1);
        float cr0 = fexp2(m0v - nm0), cr1 = fexp2(m1v - nm1);
        m0v = nm0; m1v = nm1;
        l0 *= cr0; l1 *= cr1;
#pragma unroll
        for (int nt = 0; nt < 8; nt++) {
            co[nt][0] *= cr0; co[nt][1] *= cr0;
            co[nt][2] *= cr1; co[nt][3] *= cr1;
        }

#pragma unroll
        for (int nt = 0; nt < 8; nt++) {
            cs[nt][0] = fexp2(cs[nt][0] - nm0);
            cs[nt][1] = fexp2(cs[nt][1] - nm0);
            cs[nt][2] = fexp2(cs[nt][2] - nm1);
            cs[nt][3] = fexp2(cs[nt][3] - nm1);
            l0 += cs[nt][0] + cs[nt][1];
            l1 += cs[nt][2] + cs[nt][3];
        }

#pragma unroll
        for (int ks = 0; ks < 4; ks++) {
            uint32_t aph[4], apl[4];
#pragma unroll
            for (int j = 0; j < 4; j++) {
                float x0 = cs[2 * ks + (j >> 1)][(j & 1) * 2];
                float x1 = cs[2 * ks + (j >> 1)][(j & 1) * 2 + 1];
                bf16 h0, lo0, h1, lo1;
                split2(x0, h0, lo0); split2(x1, h1, lo1);
                aph[j] = pack_bf2(h0, h1);
                apl[j] = pack_bf2(lo0, lo1);
            }
            uint32_t vh[8][2], vl[8][2];
            int vrow = ks * 16 + vr_base;
#pragma unroll
            for (int p = 0; p < 4; p++) {
                uint32_t offV = SWZ(vrow * 128 + p * 32 + vc_base);
                ldsm4t(vh[2*p][0], vh[2*p][1], vh[2*p+1][0], vh[2*p+1][1], st + 16384 + offV);
                ldsm4t(vl[2*p][0], vl[2*p][1], vl[2*p+1][0], vl[2*p+1][1], st + 24576 + offV);
            }
#pragma unroll
            for (int nt = 0; nt < 8; nt++) {
                mma_bf16(co[nt], aph, vh[nt]);
                mma_bf16(co[nt], aph, vl[nt]);
                mma_bf16(co[nt], apl, vh[nt]);
            }
        }
    }

    l0 += __shfl_xor_sync(0xffffffffu, l0, 1);
    l0 += __shfl_xor_sync(0xffffffffu, l0, 2);
    l1 += __shfl_xor_sync(0xffffffffu, l1, 1);
    l1 += __shfl_xor_sync(0xffffffffu, l1, 2);
    float i0 = 1.f / l0, i1 = 1.f / l1;
    int r0 = q0 + wq + g, r1 = r0 + 8;
#pragma unroll
    for (int nt = 0; nt < 8; nt++) {
        int col = h * 64 + nt * 8 + 2 * tig;
        float y00 = co[nt][0] * i0, y01 = co[nt][1] * i0;
        float y10 = co[nt][2] * i1, y11 = co[nt][3] * i1;
        bf16 h00, l00, h01, l01, h10, l10, h11, l11;
        split2(y00, h00, l00); split2(y01, h01, l01);
        split2(y10, h10, l10); split2(y11, h11, l11);
        size_t o0 = (size_t)(b * T_ + r0) * D_ + col;
        size_t o1 = (size_t)(b * T_ + r1) * D_ + col;
        *(__nv_bfloat162*)&g_at_hi[o0] = {h00, h01};
        *(__nv_bfloat162*)&g_at_hi[o1] = {h10, h11};
        *(__nv_bfloat162*)&g_at_lo[o0] = {l00, l01};
        *(__nv_bfloat162*)&g_at_lo[o1] = {l10, l11};
    }
}

// ---------------- heads (fused final rmsnorm): warp per output --------------
__global__ void heads_kernel(const float* __restrict__ hw,
                             const float* __restrict__ nf,
                             float* __restrict__ out) {
    int wid = threadIdx.x >> 5, lane = threadIdx.x & 31;
    int idx = blockIdx.x * 8 + wid;
    int v = idx % V_;
    int sb = idx / V_;
    int b = sb % B_;
    int s = sb / B_;
    const float4* wr = (const float4*)(hw + ((size_t)s * V_ + v) * D_);
    const float4* xv = (const float4*)(g_x + ((size_t)(b * T_ + T_ - 1)) * D_);
    const float4* nw = (const float4*)nf;
    float dot = 0.f, ss = 0.f;
#pragma unroll
    for (int j = 0; j < 6; j++) {
        float4 w4 = wr[lane + 32 * j], x4 = xv[lane + 32 * j], n4 = nw[lane + 32 * j];
        ss  += x4.x * x4.x + x4.y * x4.y + x4.z * x4.z + x4.w * x4.w;
        dot += w4.x * x4.x * n4.x + w4.y * x4.y * n4.y
             + w4.z * x4.z * n4.z + w4.w * x4.w * n4.w;
    }
#pragma unroll
    for (int o = 16; o; o >>= 1) {
        ss  += __shfl_xor_sync(0xffffffffu, ss, o);
        dot += __shfl_xor_sync(0xffffffffu, dot, o);
    }
    float inv = rsqrtf(ss * (1.0f / D_) + 1e-6f);
    if (lane == 0) out[idx] = dot * inv;
}

// ---------------- launcher -------------------------------------------------
extern "C" void kernel_launch(void* const* d_in, const int* in_sizes, int n_in,
                              void* d_out, int out_size) {
    const int*   tok    = (const int*)d_in[0];
    const int*   pos    = (const int*)d_in[1];
    const float* intent = (const float*)d_in[2];
    const float* rvq    = (const float*)d_in[3];
    const float* pe     = (const float*)d_in[4];
    const float* n1     = (const float*)d_in[5];
    const float* n2     = (const float*)d_in[6];
    const float* qkvw   = (const float*)d_in[7];
    const float* projw  = (const float*)d_in[8];
    const float* gatew  = (const float*)d_in[9];
    const float* upw    = (const float*)d_in[10];
    const float* downw  = (const float*)d_in[11];
    const float* nf     = (const float*)d_in[12];
    const float* hw     = (const float*)d_in[13];
    float* out = (float*)d_out;

    cudaFuncSetAttribute(GEMM_Q,  cudaFuncAttributeMaxDynamicSharedMemorySize, SMEM_QP);
    cudaFuncSetAttribute(GEMM_P,  cudaFuncAttributeMaxDynamicSharedMemorySize, SMEM_QP);
    cudaFuncSetAttribute(gemm_gu, cudaFuncAttributeMaxDynamicSharedMemorySize, SMEM_GU);
    cudaFuncSetAttribute(attn_mma, cudaFuncAttributeMaxDynamicSharedMemorySize, ATT_SMEM);

    float *x;
    bf16 *h_hi, *h_lo, *at_hi, *at_lo, *ff_hi, *ff_lo, *qkv_hi, *qkv_lo;
    bf16 *qw_h, *qw_l, *pw_h, *pw_l, *gw_h, *gw_l, *uw_h, *uw_l, *dw_h, *dw_l;
    cudaGetSymbolAddress((void**)&x,    g_x);
    cudaGetSymbolAddress((void**)&h_hi, g_h_hi);
    cudaGetSymbolAddress((void**)&h_lo, g_h_lo);
    cudaGetSymbolAddress((void**)&at_hi, g_at_hi);
    cudaGetSymbolAddress((void**)&at_lo, g_at_lo);
    cudaGetSymbolAddress((void**)&ff_hi, g_ff_hi);
    cudaGetSymbolAddress((void**)&ff_lo, g_ff_lo);
    cudaGetSymbolAddress((void**)&qkv_hi, g_qkv_hi);
    cudaGetSymbolAddress((void**)&qkv_lo, g_qkv_lo);
    cudaGetSymbolAddress((void**)&qw_h, g_qkvw_hi);
    cudaGetSymbolAddress((void**)&qw_l, g_qkvw_lo);
    cudaGetSymbolAddress((void**)&pw_h, g_projw_hi);
    cudaGetSymbolAddress((void**)&pw_l, g_projw_lo);
    cudaGetSymbolAddress((void**)&gw_h, g_gatew_hi);
    cudaGetSymbolAddress((void**)&gw_l, g_gatew_lo);
    cudaGetSymbolAddress((void**)&uw_h, g_upw_hi);
    cudaGetSymbolAddress((void**)&uw_l, g_upw_lo);
    cudaGetSymbolAddress((void**)&dw_h, g_downw_hi);
    cudaGetSymbolAddress((void**)&dw_l, g_downw_lo);

    split_all_kernel<<<(N8_TOT + 255) / 256, 256>>>(
        qkvw, projw, gatew, upw, downw,
        qw_h, qw_l, pw_h, pw_l, gw_h, gw_l, uw_h, uw_l, dw_h, dw_l);

    embed_kernel<<<(BT * D_ / 4 + 255) / 256, 256>>>(tok, pos, intent, rvq, pe);

    for (int l = 0; l < L_; l++) {
        rmsnorm_split_kernel<<<BT / 8, 256>>>(x, n1 + (size_t)l * D_, h_hi, h_lo);

        GEMM_Q<<<dim3(E3 / 64, BT / 128), 128, SMEM_QP>>>(
            h_hi, h_lo,
            qw_h + (size_t)l * E3 * D_, qw_l + (size_t)l * E3 * D_,
            nullptr, nullptr, qkv_hi, qkv_lo, E3, D_);

        attn_mma<<<B_ * H_ * (T_ / AQ), 128, ATT_SMEM>>>();

        GEMM_P<<<dim3(D_ / 64, BT / 128), 128, SMEM_QP>>>(
            at_hi, at_lo,
            pw_h + (size_t)l * D_ * D_, pw_l + (size_t)l * D_ * D_,
            x, x, nullptr, nullptr, D_, D_);

        rmsnorm_split_kernel<<<BT / 8, 256>>>(x, n2 + (size_t)l * D_, h_hi, h_lo);

        gemm_gu<<<dim3(FF_ / 64, BT / 64), 128, SMEM_GU>>>(
            h_hi, h_lo,
            gw_h + (size_t)l * FF_ * D_, gw_l + (size_t)l * FF_ * D_,
            uw_h + (size_t)l * FF_ * D_, uw_l + (size_t)l * FF_ * D_,
            ff_hi, ff_lo, FF_, D_);

        GEMM_P<<<dim3(D_ / 64, BT / 128), 128, SMEM_QP>>>(
            ff_hi, ff_lo,
            dw_h + (size_t)l * D_ * FF_, dw_l + (size_t)l * D_ * FF_,
            x, x, nullptr, nullptr, D_, FF_);
    }

    heads_kernel<<<S_ * B_ * V_ / 8, 256>>>(hw, nf, out);
}

// round 16
// speedup vs baseline: 1.0351x; 1.0351x over previous
#include <cuda_runtime.h>
#include <cuda_bf16.h>
#include <math.h>
#include <stdint.h>

#define B_  2
#define T_  1024
#define BT  2048
#define D_  768
#define H_  12
#define DH_ 64
#define FF_ 3072
#define L_  12
#define S_  8
#define V_  1024
#define E3  2304   // 3*D

typedef __nv_bfloat16 bf16;

// ---------------- scratch -------------------------------------------------
__device__ __align__(16) float g_x   [BT * D_];

__device__ __align__(16) bf16 g_h_hi [BT * D_];
__device__ __align__(16) bf16 g_h_lo [BT * D_];
__device__ __align__(16) bf16 g_at_hi[BT * D_];
__device__ __align__(16) bf16 g_at_lo[BT * D_];
__device__ __align__(16) bf16 g_ff_hi[BT * FF_];
__device__ __align__(16) bf16 g_ff_lo[BT * FF_];
__device__ __align__(16) bf16 g_qkv_hi[BT * E3];
__device__ __align__(16) bf16 g_qkv_lo[BT * E3];

// weight splits
__device__ __align__(16) bf16 g_qkvw_hi [L_ * E3 * D_];
__device__ __align__(16) bf16 g_qkvw_lo [L_ * E3 * D_];
__device__ __align__(16) bf16 g_projw_hi[L_ * D_ * D_];
__device__ __align__(16) bf16 g_projw_lo[L_ * D_ * D_];
__device__ __align__(16) bf16 g_gatew_hi[L_ * FF_ * D_];
__device__ __align__(16) bf16 g_gatew_lo[L_ * FF_ * D_];
__device__ __align__(16) bf16 g_upw_hi  [L_ * FF_ * D_];
__device__ __align__(16) bf16 g_upw_lo  [L_ * FF_ * D_];
__device__ __align__(16) bf16 g_downw_hi[L_ * D_ * FF_];
__device__ __align__(16) bf16 g_downw_lo[L_ * D_ * FF_];

// ---------------- helpers --------------------------------------------------
__device__ __forceinline__ uint32_t smem_u32(const void* p) {
    uint32_t a;
    asm("{ .reg .u64 t; cvta.to.shared.u64 t, %1; cvt.u32.u64 %0, t; }" : "=r"(a) : "l"(p));
    return a;
}
__device__ __forceinline__ void cp16(uint32_t dst, const void* src) {
    asm volatile("cp.async.cg.shared.global [%0], [%1], 16;" :: "r"(dst), "l"(src));
}
__device__ __forceinline__ void cp_commit() {
    asm volatile("cp.async.commit_group;" ::: "memory");
}
template<int N>
__device__ __forceinline__ void cp_wait() {
    asm volatile("cp.async.wait_group %0;" :: "n"(N) : "memory");
}
__device__ __forceinline__ void ldsm4(uint32_t& r0, uint32_t& r1, uint32_t& r2, uint32_t& r3,
                                      uint32_t addr) {
    asm volatile("ldmatrix.sync.aligned.m8n8.x4.shared.b16 {%0,%1,%2,%3}, [%4];"
                 : "=r"(r0), "=r"(r1), "=r"(r2), "=r"(r3) : "r"(addr));
}
__device__ __forceinline__ void ldsm4t(uint32_t& r0, uint32_t& r1, uint32_t& r2, uint32_t& r3,
                                       uint32_t addr) {
    asm volatile("ldmatrix.sync.aligned.m8n8.x4.trans.shared.b16 {%0,%1,%2,%3}, [%4];"
                 : "=r"(r0), "=r"(r1), "=r"(r2), "=r"(r3) : "r"(addr));
}
__device__ __forceinline__ void mma_bf16(float* c, const uint32_t* a, const uint32_t* b) {
    asm volatile(
        "mma.sync.aligned.m16n8k16.row.col.f32.bf16.bf16.f32 "
        "{%0,%1,%2,%3}, {%4,%5,%6,%7}, {%8,%9}, {%0,%1,%2,%3};"
        : "+f"(c[0]), "+f"(c[1]), "+f"(c[2]), "+f"(c[3])
        : "r"(a[0]), "r"(a[1]), "r"(a[2]), "r"(a[3]), "r"(b[0]), "r"(b[1]));
}
#define SWZ(x) ((x) ^ (((x) >> 3) & 0x70))

// fast exp on FMA pipe
__device__ __forceinline__ float fexp(float x) {
    x = fmaxf(fminf(x, 80.f), -80.f);
    float t = x * 1.4426950408889634f;
    float fl = floorf(t);
    float f = t - fl;
    float p = 1.3333558e-3f;
    p = fmaf(p, f, 9.6181291e-3f);
    p = fmaf(p, f, 5.5504109e-2f);
    p = fmaf(p, f, 2.4022651e-1f);
    p = fmaf(p, f, 6.9314718e-1f);
    p = fmaf(p, f, 1.0f);
    int e = (int)fl;
    return __int_as_float(__float_as_int(p) + (e << 23));
}
__device__ __forceinline__ float fexp2(float t) {
    t = fmaxf(fminf(t, 80.f), -80.f);
    float fl = floorf(t);
    float f = t - fl;
    float p = 1.3333558e-3f;
    p = fmaf(p, f, 9.6181291e-3f);
    p = fmaf(p, f, 5.5504109e-2f);
    p = fmaf(p, f, 2.4022651e-1f);
    p = fmaf(p, f, 6.9314718e-1f);
    p = fmaf(p, f, 1.0f);
    int e = (int)fl;
    return __int_as_float(__float_as_int(p) + (e << 23));
}
__device__ __forceinline__ void split2(float x, bf16& h, bf16& l) {
    h = __float2bfloat16_rn(x);
    l = __float2bfloat16_rn(x - __bfloat162float(h));
}
__device__ __forceinline__ float silu(float g) {
    return g / (1.f + fexp(-g));
}
__device__ __forceinline__ uint32_t pack_bf2(bf16 a, bf16 b) {
    __nv_bfloat162 t = {a, b};
    return *(uint32_t*)&t;
}

// ---------------- fused weight split ----------------------------------------
#define N8_QKV  (L_ * E3 * D_ / 8)
#define N8_PROJ (L_ * D_ * D_ / 8)
#define N8_FF   (L_ * FF_ * D_ / 8)
#define N8_TOT  (N8_QKV + N8_PROJ + 3 * N8_FF)
__global__ void split_all_kernel(
    const float* __restrict__ q, const float* __restrict__ p,
    const float* __restrict__ gt, const float* __restrict__ u,
    const float* __restrict__ dn,
    bf16* __restrict__ qh, bf16* __restrict__ ql,
    bf16* __restrict__ ph, bf16* __restrict__ pl,
    bf16* __restrict__ gh, bf16* __restrict__ gl,
    bf16* __restrict__ uh, bf16* __restrict__ ul,
    bf16* __restrict__ dh, bf16* __restrict__ dl) {
    int i = blockIdx.x * blockDim.x + threadIdx.x;
    if (i >= N8_TOT) return;
    const float* src; bf16 *hi, *lo; int j;
    if (i < N8_QKV)                      { src = q;  hi = qh; lo = ql; j = i; }
    else if (i < N8_QKV + N8_PROJ)       { src = p;  hi = ph; lo = pl; j = i - N8_QKV; }
    else if (i < N8_QKV + N8_PROJ + N8_FF)       { src = gt; hi = gh; lo = gl; j = i - N8_QKV - N8_PROJ; }
    else if (i < N8_QKV + N8_PROJ + 2 * N8_FF)   { src = u;  hi = uh; lo = ul; j = i - N8_QKV - N8_PROJ - N8_FF; }
    else                                 { src = dn; hi = dh; lo = dl; j = i - N8_QKV - N8_PROJ - 2 * N8_FF; }
    float4 v0 = __ldcs((const float4*)src + 2 * (size_t)j);
    float4 v1 = __ldcs((const float4*)src + 2 * (size_t)j + 1);
    bf16 h[8], l[8];
    split2(v0.x, h[0], l[0]); split2(v0.y, h[1], l[1]);
    split2(v0.z, h[2], l[2]); split2(v0.w, h[3], l[3]);
    split2(v1.x, h[4], l[4]); split2(v1.y, h[5], l[5]);
    split2(v1.z, h[6], l[6]); split2(v1.w, h[7], l[7]);
    uint4 hv = make_uint4(pack_bf2(h[0], h[1]), pack_bf2(h[2], h[3]),
                          pack_bf2(h[4], h[5]), pack_bf2(h[6], h[7]));
    uint4 lv = make_uint4(pack_bf2(l[0], l[1]), pack_bf2(l[2], l[3]),
                          pack_bf2(l[4], l[5]), pack_bf2(l[6], l[7]));
    __stcs((uint4*)hi + j, hv);
    __stcs((uint4*)lo + j, lv);
}

// ---------------- embedding ------------------------------------------------
__global__ void embed_kernel(const int* __restrict__ tok,
                             const int* __restrict__ pos,
                             const float* __restrict__ intent,
                             const float* __restrict__ rvq,
                             const float* __restrict__ pe) {
    int i4 = blockIdx.x * blockDim.x + threadIdx.x;
    if (i4 >= BT * D_ / 4) return;
    int row = i4 / (D_ / 4), d4 = i4 % (D_ / 4);
    int b = row / T_;
    float4 acc = ((const float4*)(pe + (size_t)pos[row] * D_))[d4];
    float4 it = ((const float4*)(intent + (size_t)b * D_))[d4];
    acc.x += it.x; acc.y += it.y; acc.z += it.z; acc.w += it.w;
    const int* tk = tok + (size_t)row * S_;
#pragma unroll
    for (int s = 0; s < S_; s++) {
        float4 rv = ((const float4*)(rvq + ((size_t)s * V_ + tk[s]) * D_))[d4];
        acc.x += rv.x; acc.y += rv.y; acc.z += rv.z; acc.w += rv.w;
    }
    ((float4*)g_x)[i4] = acc;
}

// ---------------- rmsnorm -> hi/lo bf16 (warp per row) ----------------------
__global__ void rmsnorm_split_kernel(const float* __restrict__ src,
                                     const float* __restrict__ w,
                                     bf16* __restrict__ hi, bf16* __restrict__ lo) {
    int gw = (blockIdx.x * blockDim.x + threadIdx.x) >> 5;
    int lane = threadIdx.x & 31;
    const float4* x4 = (const float4*)(src + (size_t)gw * D_);
    const float4* w4 = (const float4*)w;
    float4 v[6];
    float ss = 0.f;
#pragma unroll
    for (int j = 0; j < 6; j++) {
        v[j] = x4[lane + 32 * j];
        ss += v[j].x * v[j].x + v[j].y * v[j].y + v[j].z * v[j].z + v[j].w * v[j].w;
    }
#pragma unroll
    for (int o = 16; o; o >>= 1) ss += __shfl_xor_sync(0xffffffffu, ss, o);
    float inv = rsqrtf(ss * (1.0f / D_) + 1e-6f);
    uint2* hp = (uint2*)(hi + (size_t)gw * D_);
    uint2* lp = (uint2*)(lo + (size_t)gw * D_);
#pragma unroll
    for (int j = 0; j < 6; j++) {
        float4 wv = w4[lane + 32 * j];
        float y0 = v[j].x * inv * wv.x, y1 = v[j].y * inv * wv.y;
        float y2 = v[j].z * inv * wv.z, y3 = v[j].w * inv * wv.w;
        bf16 h0, l0, h1, l1, h2, l2, h3, l3;
        split2(y0, h0, l0); split2(y1, h1, l1);
        split2(y2, h2, l2); split2(y3, h3, l3);
        hp[lane + 32 * j] = make_uint2(pack_bf2(h0, h1), pack_bf2(h2, h3));
        lp[lane + 32 * j] = make_uint2(pack_bf2(l0, l1), pack_bf2(l2, l3));
    }
}

// ---------------- HMMA bf16x3 GEMM (R14 issue-before-wait pipeline) ---------
// MODE 1: C = res + A*W^T fp32; MODE 3: A*W^T -> split bf16 out
template<int BM, int BN, int WM, int WN, int MODE, int NS>
__global__ __launch_bounds__(WM * WN * 32)
void gemm_mma(const bf16* __restrict__ Ah, const bf16* __restrict__ Al,
              const bf16* __restrict__ Wh, const bf16* __restrict__ Wl,
              float* __restrict__ C, const float* __restrict__ res,
              bf16* __restrict__ out_hi, bf16* __restrict__ out_lo,
              int N, int K) {
    constexpr int NT   = WM * WN * 32;
    constexpr int WTM  = BM / WM;
    constexpr int WTN  = BN / WN;
    constexpr int MT   = WTM / 16;
    constexpr int NTt  = WTN / 8;
    constexpr int ASZ  = BM * 128;
    constexpr int WSZ  = BN * 128;
    constexpr int STAGE = 2 * ASZ + 2 * WSZ;

    extern __shared__ char smem[];
    uint32_t sb = smem_u32(smem);
    int tid = threadIdx.x, lane = tid & 31, w = tid >> 5;
    int mw = w / WN, nw = w % WN;
    int m0 = blockIdx.y * BM, n0 = blockIdx.x * BN;

    float c[MT][NTt][4];
#pragma unroll
    for (int i = 0; i < MT; i++)
#pragma unroll
        for (int j = 0; j < NTt; j++)
#pragma unroll
            for (int q = 0; q < 4; q++) c[i][j][q] = 0.f;

    int nst = K >> 6;
    int a_row = (lane & 15);
    int a_kof = (lane >> 4) * 16;
    int b_row = (lane & 7) + ((lane >> 4) << 3);
    int b_kof = ((lane >> 3) & 1) * 16;

    auto load_stage = [&](int stage_idx, int k0) {
        uint32_t buf = sb + (stage_idx % NS) * STAGE;
#pragma unroll
        for (int j = 0; j < BM * 8 / NT; j++) {
            int idx = tid + j * NT;
            int row = idx >> 3, q = idx & 7;
            uint32_t so = SWZ(row * 128 + q * 16);
            size_t ga = (size_t)(m0 + row) * K + k0 + q * 8;
            cp16(buf + so, Ah + ga);
            cp16(buf + ASZ + so, Al + ga);
        }
#pragma unroll
        for (int j = 0; j < BN * 8 / NT; j++) {
            int idx = tid + j * NT;
            int row = idx >> 3, q = idx & 7;
            uint32_t so = SWZ(row * 128 + q * 16);
            size_t gw = (size_t)(n0 + row) * K + k0 + q * 8;
            cp16(buf + 2 * ASZ + so, Wh + gw);
            cp16(buf + 2 * ASZ + WSZ + so, Wl + gw);
        }
        cp_commit();
    };

    load_stage(0, 0);
    if (NS >= 3 && nst > 1) load_stage(1, 64);

    for (int i = 0; i < nst; i++) {
        int nxt = i + (NS - 1);
        if (nxt < nst) { load_stage(nxt, nxt << 6); cp_wait<NS - 1>(); }
        else if (i + 1 < nst) { cp_wait<1>(); }
        else { cp_wait<0>(); }
        __syncthreads();

        uint32_t buf = sb + (i % NS) * STAGE;
        uint32_t sAh = buf, sAl = buf + ASZ, sWh = buf + 2 * ASZ, sWl = buf + 2 * ASZ + WSZ;

#pragma unroll
        for (int ks = 0; ks < 4; ks++) {
            uint32_t ah[MT][4], al[MT][4], bh[NTt][2], bl[NTt][2];
#pragma unroll
            for (int mt = 0; mt < MT; mt++) {
                uint32_t off = SWZ((mw * WTM + mt * 16 + a_row) * 128 + ks * 32 + a_kof);
                ldsm4(ah[mt][0], ah[mt][1], ah[mt][2], ah[mt][3], sAh + off);
                ldsm4(al[mt][0], al[mt][1], al[mt][2], al[mt][3], sAl + off);
            }
#pragma unroll
            for (int p = 0; p < NTt / 2; p++) {
                uint32_t off = SWZ((nw * WTN + p * 16 + b_row) * 128 + ks * 32 + b_kof);
                ldsm4(bh[2*p][0], bh[2*p][1], bh[2*p+1][0], bh[2*p+1][1], sWh + off);
                ldsm4(bl[2*p][0], bl[2*p][1], bl[2*p+1][0], bl[2*p+1][1], sWl + off);
            }
#pragma unroll
            for (int mt = 0; mt < MT; mt++)
#pragma unroll
                for (int nt = 0; nt < NTt; nt++) {
                    mma_bf16(c[mt][nt], ah[mt], bh[nt]);
                    mma_bf16(c[mt][nt], ah[mt], bl[nt]);
                    mma_bf16(c[mt][nt], al[mt], bh[nt]);
                }
        }
        __syncthreads();
    }

    int g = lane >> 2, tig = lane & 3;
#pragma unroll
    for (int mt = 0; mt < MT; mt++) {
        int row = m0 + mw * WTM + mt * 16 + g;
#pragma unroll
        for (int nt = 0; nt < NTt; nt++) {
            int col = n0 + nw * WTN + nt * 8 + tig * 2;
            size_t o0 = (size_t)row * N + col;
            size_t o1 = o0 + (size_t)8 * N;
            float2 v0 = make_float2(c[mt][nt][0], c[mt][nt][1]);
            float2 v1 = make_float2(c[mt][nt][2], c[mt][nt][3]);
            if (MODE == 1) {
                float2 r0 = *(const float2*)&res[o0];
                float2 r1 = *(const float2*)&res[o1];
                v0.x += r0.x; v0.y += r0.y; v1.x += r1.x; v1.y += r1.y;
                *(float2*)&C[o0] = v0;
                *(float2*)&C[o1] = v1;
            } else {
                bf16 h00, l00, h01, l01, h10, l10, h11, l11;
                split2(v0.x, h00, l00); split2(v0.y, h01, l01);
                split2(v1.x, h10, l10); split2(v1.y, h11, l11);
                *(__nv_bfloat162*)&out_hi[o0] = {h00, h01};
                *(__nv_bfloat162*)&out_hi[o1] = {h10, h11};
                *(__nv_bfloat162*)&out_lo[o0] = {l00, l01};
                *(__nv_bfloat162*)&out_lo[o1] = {l10, l11};
            }
        }
    }
}

// 128-thread shapes for 2 CTAs/SM
#define GEMM_Q   gemm_mma<128, 64, 2, 2, 3, 2>
#define GEMM_P   gemm_mma<128, 64, 2, 2, 1, 2>
#define SMEM_QP  (2 * (2 * 128 * 128 + 2 * 64 * 128))   // 98304

// ---------------- fused gate+up GEMM (R14 pipeline) -------------------------
#define GU_ASZ  8192
#define GU_STAGE (6 * GU_ASZ)
#define SMEM_GU (2 * GU_STAGE)            // 98304
__global__ __launch_bounds__(128)
void gemm_gu(const bf16* __restrict__ Ah, const bf16* __restrict__ Al,
             const bf16* __restrict__ Gh, const bf16* __restrict__ Gl,
             const bf16* __restrict__ Uh, const bf16* __restrict__ Ul,
             bf16* __restrict__ out_hi, bf16* __restrict__ out_lo,
             int N, int K) {
    extern __shared__ char smem[];
    uint32_t sb = smem_u32(smem);
    int tid = threadIdx.x, lane = tid & 31, w = tid >> 5;
    int mw = w >> 1, nw = w & 1;
    int m0 = blockIdx.y * 64, n0 = blockIdx.x * 64;

    float cg[2][4][4], cu[2][4][4];
#pragma unroll
    for (int i = 0; i < 2; i++)
#pragma unroll
        for (int j = 0; j < 4; j++)
#pragma unroll
            for (int q = 0; q < 4; q++) { cg[i][j][q] = 0.f; cu[i][j][q] = 0.f; }

    int nst = K >> 6;
    int a_row = lane & 15, a_kof = (lane >> 4) * 16;
    int b_row = (lane & 7) + ((lane >> 4) << 3), b_kof = ((lane >> 3) & 1) * 16;

    auto load_stage = [&](int si, int k0) {
        uint32_t buf = sb + (si & 1) * GU_STAGE;
#pragma unroll
        for (int j = 0; j < 4; j++) {
            int idx = tid + j * 128;
            int row = idx >> 3, q = idx & 7;
            uint32_t so = SWZ(row * 128 + q * 16);
            size_t ga = (size_t)(m0 + row) * K + k0 + q * 8;
            size_t gw = (size_t)(n0 + row) * K + k0 + q * 8;
            cp16(buf + so, Ah + ga);
            cp16(buf + GU_ASZ + so, Al + ga);
            cp16(buf + 2 * GU_ASZ + so, Gh + gw);
            cp16(buf + 3 * GU_ASZ + so, Gl + gw);
            cp16(buf + 4 * GU_ASZ + so, Uh + gw);
            cp16(buf + 5 * GU_ASZ + so, Ul + gw);
        }
        cp_commit();
    };

    load_stage(0, 0);

    for (int i = 0; i < nst; i++) {
        if (i + 1 < nst) { load_stage(i + 1, (i + 1) << 6); cp_wait<1>(); }
        else             { cp_wait<0>(); }
        __syncthreads();

        uint32_t buf = sb + (i & 1) * GU_STAGE;

#pragma unroll
        for (int ks = 0; ks < 4; ks++) {
            uint32_t ah[2][4], al[2][4], bh[4][2], bl[4][2];
#pragma unroll
            for (int mt = 0; mt < 2; mt++) {
                uint32_t off = SWZ((mw * 32 + mt * 16 + a_row) * 128 + ks * 32 + a_kof);
                ldsm4(ah[mt][0], ah[mt][1], ah[mt][2], ah[mt][3], buf + off);
                ldsm4(al[mt][0], al[mt][1], al[mt][2], al[mt][3], buf + GU_ASZ + off);
            }
#pragma unroll
            for (int p = 0; p < 2; p++) {
                uint32_t off = SWZ((nw * 32 + p * 16 + b_row) * 128 + ks * 32 + b_kof);
                ldsm4(bh[2*p][0], bh[2*p][1], bh[2*p+1][0], bh[2*p+1][1], buf + 2 * GU_ASZ + off);
                ldsm4(bl[2*p][0], bl[2*p][1], bl[2*p+1][0], bl[2*p+1][1], buf + 3 * GU_ASZ + off);
            }
#pragma unroll
            for (int mt = 0; mt < 2; mt++)
#pragma unroll
                for (int nt = 0; nt < 4; nt++) {
                    mma_bf16(cg[mt][nt], ah[mt], bh[nt]);
                    mma_bf16(cg[mt][nt], ah[mt], bl[nt]);
                    mma_bf16(cg[mt][nt], al[mt], bh[nt]);
                }
#pragma unroll
            for (int p = 0; p < 2; p++) {
                uint32_t off = SWZ((nw * 32 + p * 16 + b_row) * 128 + ks * 32 + b_kof);
                ldsm4(bh[2*p][0], bh[2*p][1], bh[2*p+1][0], bh[2*p+1][1], buf + 4 * GU_ASZ + off);
                ldsm4(bl[2*p][0], bl[2*p][1], bl[2*p+1][0], bl[2*p+1][1], buf + 5 * GU_ASZ + off);
            }
#pragma unroll
            for (int mt = 0; mt < 2; mt++)
#pragma unroll
                for (int nt = 0; nt < 4; nt++) {
                    mma_bf16(cu[mt][nt], ah[mt], bh[nt]);
                    mma_bf16(cu[mt][nt], ah[mt], bl[nt]);
                    mma_bf16(cu[mt][nt], al[mt], bh[nt]);
                }
        }
        __syncthreads();
    }

    int g = lane >> 2, tig = lane & 3;
#pragma unroll
    for (int mt = 0; mt < 2; mt++) {
        int row = m0 + mw * 32 + mt * 16 + g;
#pragma unroll
        for (int nt = 0; nt < 4; nt++) {
            int col = n0 + nw * 32 + nt * 8 + tig * 2;
            size_t o0 = (size_t)row * N + col;
            size_t o1 = o0 + (size_t)8 * N;
            float y00 = silu(cg[mt][nt][0]) * cu[mt][nt][0];
            float y01 = silu(cg[mt][nt][1]) * cu[mt][nt][1];
            float y10 = silu(cg[mt][nt][2]) * cu[mt][nt][2];
            float y11 = silu(cg[mt][nt][3]) * cu[mt][nt][3];
            bf16 h00, l00, h01, l01, h10, l10, h11, l11;
            split2(y00, h00, l00); split2(y01, h01, l01);
            split2(y10, h10, l10); split2(y11, h11, l11);
            *(__nv_bfloat162*)&out_hi[o0] = {h00, h01};
            *(__nv_bfloat162*)&out_hi[o1] = {h10, h11};
            *(__nv_bfloat162*)&out_lo[o0] = {l00, l01};
            *(__nv_bfloat162*)&out_lo[o1] = {l10, l11};
        }
    }
}

// ---------------- HMMA flash attention (AQ=64, 3-stage, single-sync) --------
#define AQ 64
#define AK 64
#define ATT_SMEM (16384 + 3 * 32768)    // 114688
#define SC2 0.18033688f    // 0.125 * log2(e)
__global__ __launch_bounds__(128)
void attn_mma() {
    extern __shared__ char smem[];
    uint32_t sb = smem_u32(smem);
    int tid = threadIdx.x, lane = tid & 31, w = tid >> 5;
    int bid = blockIdx.x;
    int bh = bid % (B_ * H_);
    int qt = (T_ / AQ - 1) - bid / (B_ * H_);
    int h = bh % H_, b = bh / H_;
    int q0 = qt * AQ;
    int wq = w * 16;
    int g = lane >> 2, tig = lane & 3;
    int a_row = lane & 15, a_kof = (lane >> 4) * 16;
    int b_row = (lane & 7) + ((lane >> 4) << 3), b_kof = ((lane >> 3) & 1) * 16;
    int vr_base = (lane & 7) + ((lane >> 3) & 1) * 8;
    int vc_base = ((lane >> 4) & 1) * 16;

    {
        size_t base = (size_t)(b * T_ + q0) * E3 + h * 64;
#pragma unroll
        for (int j = 0; j < 4; j++) {
            int idx = tid + j * 128;
            int row = idx >> 3, q = idx & 7;
            uint32_t so = SWZ(row * 128 + q * 16);
            cp16(sb + so,        g_qkv_hi + base + (size_t)row * E3 + q * 8);
            cp16(sb + 8192 + so, g_qkv_lo + base + (size_t)row * E3 + q * 8);
        }
        cp_commit();
    }

    auto load_kv = [&](int t) {
        uint32_t st = sb + 16384 + (t % 3) * 32768;
        int k0 = t * AK;
        size_t kb = (size_t)(b * T_ + k0) * E3 + D_ + h * 64;
#pragma unroll
        for (int j = 0; j < 4; j++) {
            int idx = tid + j * 128;
            int row = idx >> 3, q = idx & 7;
            uint32_t so = SWZ(row * 128 + q * 16);
            cp16(st + so,         g_qkv_hi + kb + (size_t)row * E3 + q * 8);
            cp16(st + 8192 + so,  g_qkv_lo + kb + (size_t)row * E3 + q * 8);
            cp16(st + 16384 + so, g_qkv_hi + kb + D_ + (size_t)row * E3 + q * 8);
            cp16(st + 24576 + so, g_qkv_lo + kb + D_ + (size_t)row * E3 + q * 8);
        }
        cp_commit();
    };

    int ntiles = qt + 1;
    load_kv(0);
    if (ntiles > 1) load_kv(1);

    float co[8][4];
#pragma unroll
    for (int nt = 0; nt < 8; nt++)
#pragma unroll
        for (int q = 0; q < 4; q++) co[nt][q] = 0.f;
    float m0v = -INFINITY, m1v = -INFINITY, l0 = 0.f, l1 = 0.f;

    for (int t = 0; t < ntiles; t++) {
        if (t + 1 < ntiles) { cp_wait<1>(); }
        else                { cp_wait<0>(); }
        __syncthreads();
        if (t + 2 < ntiles) load_kv(t + 2);
        uint32_t st = sb + 16384 + (t % 3) * 32768;

        float cs[8][4];
#pragma unroll
        for (int nt = 0; nt < 8; nt++)
#pragma unroll
            for (int q = 0; q < 4; q++) cs[nt][q] = 0.f;
#pragma unroll
        for (int ks = 0; ks < 4; ks++) {
            uint32_t ah[4], al[4], kh[8][2], kl[8][2];
            uint32_t offA = SWZ((wq + a_row) * 128 + ks * 32 + a_kof);
            ldsm4(ah[0], ah[1], ah[2], ah[3], sb + offA);
            ldsm4(al[0], al[1], al[2], al[3], sb + 8192 + offA);
#pragma unroll
            for (int p = 0; p < 4; p++) {
                uint32_t offB = SWZ((p * 16 + b_row) * 128 + ks * 32 + b_kof);
                ldsm4(kh[2*p][0], kh[2*p][1], kh[2*p+1][0], kh[2*p+1][1], st + offB);
                ldsm4(kl[2*p][0], kl[2*p][1], kl[2*p+1][0], kl[2*p+1][1], st + 8192 + offB);
            }
#pragma unroll
            for (int nt = 0; nt < 8; nt++) {
                mma_bf16(cs[nt], ah, kh[nt]);
                mma_bf16(cs[nt], ah, kl[nt]);
                mma_bf16(cs[nt], al, kh[nt]);
            }
        }

        int k0 = t * AK;
        bool partial = (t == qt);
        int r0 = q0 + wq + g, r1 = r0 + 8;
#pragma unroll
        for (int nt = 0; nt < 8; nt++) {
#pragma unroll
            for (int q = 0; q < 4; q++) cs[nt][q] *= SC2;
            if (partial) {
                int c0 = k0 + nt * 8 + 2 * tig, c1 = c0 + 1;
                if (c0 > r0) cs[nt][0] = -INFINITY;
                if (c1 > r0) cs[nt][1] = -INFINITY;
                if (c0 > r1) cs[nt][2] = -INFINITY;
                if (c1 > r1) cs[nt][3] = -INFINITY;
            }
        }

        float mx0 = -INFINITY, mx1 = -INFINITY;
#pragma unroll
        for (int nt = 0; nt < 8; nt++) {
            mx0 = fmaxf(mx0, fmaxf(cs[nt][0], cs[nt][1]));
            mx1 = fmaxf(mx1, fmaxf(cs[nt][2], cs[nt][3]));
        }
        mx0 = fmaxf(mx0, __shfl_xor_sync(0xffffffffu, mx0, 1));
        mx0 = fmaxf(mx0, __shfl_xor_sync(0xffffffffu, mx0, 2));
        mx1 = fmaxf(mx1, __shfl_xor_sync(0xffffffffu, mx1, 1));
        mx1 = fmaxf(mx1, __shfl_xor_sync(0xffffffffu, mx1, 2));

        float nm0 = fmaxf(m0v, mx0), nm1 = fmaxf(m1v, mx1);
        float cr0 = fexp2(m0v - nm0), cr1 = fexp2(m1v - nm1);
        m0v = nm0; m1v = nm1;
        l0 *= cr0; l1 *= cr1;
#pragma unroll
        for (int nt = 0; nt < 8; nt++) {
            co[nt][0] *= cr0; co[nt][1] *= cr0;
            co[nt][2] *= cr1; co[nt][3] *= cr1;
        }

#pragma unroll
        for (int nt = 0; nt < 8; nt++) {
            cs[nt][0] = fexp2(cs[nt][0] - nm0);
            cs[nt][1] = fexp2(cs[nt][1] - nm0);
            cs[nt][2] = fexp2(cs[nt][2] - nm1);
            cs[nt][3] = fexp2(cs[nt][3] - nm1);
            l0 += cs[nt][0] + cs[nt][1];
            l1 += cs[nt][2] + cs[nt][3];
        }

#pragma unroll
        for (int ks = 0; ks < 4; ks++) {
            uint32_t aph[4], apl[4];
#pragma unroll
            for (int j = 0; j < 4; j++) {
                float x0 = cs[2 * ks + (j >> 1)][(j & 1) * 2];
                float x1 = cs[2 * ks + (j >> 1)][(j & 1) * 2 + 1];
                bf16 h0, lo0, h1, lo1;
                split2(x0, h0, lo0); split2(x1, h1, lo1);
                aph[j] = pack_bf2(h0, h1);
                apl[j] = pack_bf2(lo0, lo1);
            }
            uint32_t vh[8][2], vl[8][2];
            int vrow = ks * 16 + vr_base;
#pragma unroll
            for (int p = 0; p < 4; p++) {
                uint32_t offV = SWZ(vrow * 128 + p * 32 + vc_base);
                ldsm4t(vh[2*p][0], vh[2*p][1], vh[2*p+1][0], vh[2*p+1][1], st + 16384 + offV);
                ldsm4t(vl[2*p][0], vl[2*p][1], vl[2*p+1][0], vl[2*p+1][1], st + 24576 + offV);
            }
#pragma unroll
            for (int nt = 0; nt < 8; nt++) {
                mma_bf16(co[nt], aph, vh[nt]);
                mma_bf16(co[nt], aph, vl[nt]);
                mma_bf16(co[nt], apl, vh[nt]);
            }
        }
    }

    l0 += __shfl_xor_sync(0xffffffffu, l0, 1);
    l0 += __shfl_xor_sync(0xffffffffu, l0, 2);
    l1 += __shfl_xor_sync(0xffffffffu, l1, 1);
    l1 += __shfl_xor_sync(0xffffffffu, l1, 2);
    float i0 = 1.f / l0, i1 = 1.f / l1;
    int r0 = q0 + wq + g, r1 = r0 + 8;
#pragma unroll
    for (int nt = 0; nt < 8; nt++) {
        int col = h * 64 + nt * 8 + 2 * tig;
        float y00 = co[nt][0] * i0, y01 = co[nt][1] * i0;
        float y10 = co[nt][2] * i1, y11 = co[nt][3] * i1;
        bf16 h00, l00, h01, l01, h10, l10, h11, l11;
        split2(y00, h00, l00); split2(y01, h01, l01);
        split2(y10, h10, l10); split2(y11, h11, l11);
        size_t o0 = (size_t)(b * T_ + r0) * D_ + col;
        size_t o1 = (size_t)(b * T_ + r1) * D_ + col;
        *(__nv_bfloat162*)&g_at_hi[o0] = {h00, h01};
        *(__nv_bfloat162*)&g_at_hi[o1] = {h10, h11};
        *(__nv_bfloat162*)&g_at_lo[o0] = {l00, l01};
        *(__nv_bfloat162*)&g_at_lo[o1] = {l10, l11};
    }
}

// ---------------- heads (fused final rmsnorm): warp per output --------------
__global__ void heads_kernel(const float* __restrict__ hw,
                             const float* __restrict__ nf,
                             float* __restrict__ out) {
    int wid = threadIdx.x >> 5, lane = threadIdx.x & 31;
    int idx = blockIdx.x * 8 + wid;
    int v = idx % V_;
    int sb = idx / V_;
    int b = sb % B_;
    int s = sb / B_;
    const float4* wr = (const float4*)(hw + ((size_t)s * V_ + v) * D_);
    const float4* xv = (const float4*)(g_x + ((size_t)(b * T_ + T_ - 1)) * D_);
    const float4* nw = (const float4*)nf;
    float dot = 0.f, ss = 0.f;
#pragma unroll
    for (int j = 0; j < 6; j++) {
        float4 w4 = wr[lane + 32 * j], x4 = xv[lane + 32 * j], n4 = nw[lane + 32 * j];
        ss  += x4.x * x4.x + x4.y * x4.y + x4.z * x4.z + x4.w * x4.w;
        dot += w4.x * x4.x * n4.x + w4.y * x4.y * n4.y
             + w4.z * x4.z * n4.z + w4.w * x4.w * n4.w;
    }
#pragma unroll
    for (int o = 16; o; o >>= 1) {
        ss  += __shfl_xor_sync(0xffffffffu, ss, o);
        dot += __shfl_xor_sync(0xffffffffu, dot, o);
    }
    float inv = rsqrtf(ss * (1.0f / D_) + 1e-6f);
    if (lane == 0) out[idx] = dot * inv;
}

// ---------------- launcher -------------------------------------------------
extern "C" void kernel_launch(void* const* d_in, const int* in_sizes, int n_in,
                              void* d_out, int out_size) {
    const int*   tok    = (const int*)d_in[0];
    const int*   pos    = (const int*)d_in[1];
    const float* intent = (const float*)d_in[2];
    const float* rvq    = (const float*)d_in[3];
    const float* pe     = (const float*)d_in[4];
    const float* n1     = (const float*)d_in[5];
    const float* n2     = (const float*)d_in[6];
    const float* qkvw   = (const float*)d_in[7];
    const float* projw  = (const float*)d_in[8];
    const float* gatew  = (const float*)d_in[9];
    const float* upw    = (const float*)d_in[10];
    const float* downw  = (const float*)d_in[11];
    const float* nf     = (const float*)d_in[12];
    const float* hw     = (const float*)d_in[13];
    float* out = (float*)d_out;

    cudaFuncSetAttribute(GEMM_Q,  cudaFuncAttributeMaxDynamicSharedMemorySize, SMEM_QP);
    cudaFuncSetAttribute(GEMM_P,  cudaFuncAttributeMaxDynamicSharedMemorySize, SMEM_QP);
    cudaFuncSetAttribute(gemm_gu, cudaFuncAttributeMaxDynamicSharedMemorySize, SMEM_GU);
    cudaFuncSetAttribute(attn_mma, cudaFuncAttributeMaxDynamicSharedMemorySize, ATT_SMEM);

    float *x;
    bf16 *h_hi, *h_lo, *at_hi, *at_lo, *ff_hi, *ff_lo, *qkv_hi, *qkv_lo;
    bf16 *qw_h, *qw_l, *pw_h, *pw_l, *gw_h, *gw_l, *uw_h, *uw_l, *dw_h, *dw_l;
    cudaGetSymbolAddress((void**)&x,    g_x);
    cudaGetSymbolAddress((void**)&h_hi, g_h_hi);
    cudaGetSymbolAddress((void**)&h_lo, g_h_lo);
    cudaGetSymbolAddress((void**)&at_hi, g_at_hi);
    cudaGetSymbolAddress((void**)&at_lo, g_at_lo);
    cudaGetSymbolAddress((void**)&ff_hi, g_ff_hi);
    cudaGetSymbolAddress((void**)&ff_lo, g_ff_lo);
    cudaGetSymbolAddress((void**)&qkv_hi, g_qkv_hi);
    cudaGetSymbolAddress((void**)&qkv_lo, g_qkv_lo);
    cudaGetSymbolAddress((void**)&qw_h, g_qkvw_hi);
    cudaGetSymbolAddress((void**)&qw_l, g_qkvw_lo);
    cudaGetSymbolAddress((void**)&pw_h, g_projw_hi);
    cudaGetSymbolAddress((void**)&pw_l, g_projw_lo);
    cudaGetSymbolAddress((void**)&gw_h, g_gatew_hi);
    cudaGetSymbolAddress((void**)&gw_l, g_gatew_lo);
    cudaGetSymbolAddress((void**)&uw_h, g_upw_hi);
    cudaGetSymbolAddress((void**)&uw_l, g_upw_lo);
    cudaGetSymbolAddress((void**)&dw_h, g_downw_hi);
    cudaGetSymbolAddress((void**)&dw_l, g_downw_lo);

    split_all_kernel<<<(N8_TOT + 255) / 256, 256>>>(
        qkvw, projw, gatew, upw, downw,
        qw_h, qw_l, pw_h, pw_l, gw_h, gw_l, uw_h, uw_l, dw_h, dw_l);

    embed_kernel<<<(BT * D_ / 4 + 255) / 256, 256>>>(tok, pos, intent, rvq, pe);

    for (int l = 0; l < L_; l++) {
        rmsnorm_split_kernel<<<BT / 8, 256>>>(x, n1 + (size_t)l * D_, h_hi, h_lo);

        GEMM_Q<<<dim3(E3 / 64, BT / 128), 128, SMEM_QP>>>(
            h_hi, h_lo,
            qw_h + (size_t)l * E3 * D_, qw_l + (size_t)l * E3 * D_,
            nullptr, nullptr, qkv_hi, qkv_lo, E3, D_);

        attn_mma<<<B_ * H_ * (T_ / AQ), 128, ATT_SMEM>>>();

        GEMM_P<<<dim3(D_ / 64, BT / 128), 128, SMEM_QP>>>(
            at_hi, at_lo,
            pw_h + (size_t)l * D_ * D_, pw_l + (size_t)l * D_ * D_,
            x, x, nullptr, nullptr, D_, D_);

        rmsnorm_split_kernel<<<BT / 8, 256>>>(x, n2 + (size_t)l * D_, h_hi, h_lo);

        gemm_gu<<<dim3(FF_ / 64, BT / 64), 128, SMEM_GU>>>(
            h_hi, h_lo,
            gw_h + (size_t)l * FF_ * D_, gw_l + (size_t)l * FF_ * D_,
            uw_h + (size_t)l * FF_ * D_, uw_l + (size_t)l * FF_ * D_,
            ff_hi, ff_lo, FF_, D_);

        GEMM_P<<<dim3(D_ / 64, BT / 128), 128, SMEM_QP>>>(
            ff_hi, ff_lo,
            dw_h + (size_t)l * D_ * FF_, dw_l + (size_t)l * D_ * FF_,
            x, x, nullptr, nullptr, D_, FF_);
    }

    heads_kernel<<<S_ * B_ * V_ / 8, 256>>>(hw, nf, out);
}